// round 3
// baseline (speedup 1.0000x reference)
#include <cuda_runtime.h>
#include <cstdint>

#define N_NODES 50000
#define N_EDGES 600000
#define DIM 128

// ---- device scratch (static allocs are allowed) ----
__device__ float g_denom[N_NODES];
__device__ int g_cnt[N_NODES];        // per-node degree histogram
__device__ int g_off[N_NODES + 1];    // CSR row offsets
__device__ int g_cursor[N_NODES];     // scatter cursors
__device__ int g_scol[N_EDGES];       // sources sorted by destination

// ---------------------------------------------------------------------------
// K0: zero histogram
// ---------------------------------------------------------------------------
__global__ void zero_cnt_kernel() {
    int idx = blockIdx.x * blockDim.x + threadIdx.x;
    int stride = gridDim.x * blockDim.x;
    for (int i = idx; i < N_NODES; i += stride) g_cnt[i] = 0;
}

// ---------------------------------------------------------------------------
// K1: degree histogram over destination nodes
// ---------------------------------------------------------------------------
__global__ void hist_kernel(const int* __restrict__ edges) {
    int idx = blockIdx.x * blockDim.x + threadIdx.x;
    int stride = gridDim.x * blockDim.x;
    for (int e = idx; e < N_EDGES; e += stride) {
        int r = edges[e];
        if ((unsigned)r < N_NODES) atomicAdd(&g_cnt[r], 1);
    }
}

// ---------------------------------------------------------------------------
// K2: exclusive scan of 50k degrees (single block, 1024 threads)
// ---------------------------------------------------------------------------
__global__ void __launch_bounds__(1024, 1) scan_kernel() {
    __shared__ int sums[1024];
    const int PER = (N_NODES + 1023) / 1024;  // 49
    int t = threadIdx.x;
    int base = t * PER;

    int sum = 0;
    for (int i = 0; i < PER; i++) {
        int idx = base + i;
        if (idx < N_NODES) sum += g_cnt[idx];
    }
    sums[t] = sum;
    __syncthreads();

    // Hillis-Steele inclusive scan over 1024 partials
    for (int o = 1; o < 1024; o <<= 1) {
        int v = (t >= o) ? sums[t - o] : 0;
        __syncthreads();
        sums[t] += v;
        __syncthreads();
    }

    int run = (t == 0) ? 0 : sums[t - 1];  // exclusive offset for this chunk
    for (int i = 0; i < PER; i++) {
        int idx = base + i;
        if (idx < N_NODES) {
            g_off[idx] = run;
            g_cursor[idx] = run;
            run += g_cnt[idx];
        }
    }
    if (t == 1023) g_off[N_NODES] = run;
}

// ---------------------------------------------------------------------------
// K3: scatter sources into destination-sorted order
// ---------------------------------------------------------------------------
__global__ void scatter_kernel(const int* __restrict__ edges) {
    int idx = blockIdx.x * blockDim.x + threadIdx.x;
    int stride = gridDim.x * blockDim.x;
    for (int e = idx; e < N_EDGES; e += stride) {
        int r = edges[e];
        int c = edges[N_EDGES + e];
        if ((unsigned)r >= N_NODES || (unsigned)c >= N_NODES) continue;
        int pos = atomicAdd(&g_cursor[r], 1);
        g_scol[pos] = c;
    }
}

// ---------------------------------------------------------------------------
// K4: one warp per destination node — attention + aggregation, no atomics.
//   acc  = sum_e exp(<emb[n], emb[src_e]>) * emb[src_e]
//   denom= sum_e exp(...)
// ---------------------------------------------------------------------------
__global__ void segment_kernel(const float4* __restrict__ emb4,
                               float* __restrict__ agg) {
    int n = (blockIdx.x * blockDim.x + threadIdx.x) >> 5;
    int lane = threadIdx.x & 31;
    if (n >= N_NODES) return;

    int start = g_off[n];
    int end = g_off[n + 1];
    int deg = end - start;

    float4 a = emb4[(size_t)n * 32 + lane];
    float4 acc = make_float4(0.f, 0.f, 0.f, 0.f);
    float denom = 0.f;

    // preload up to 32 source indices (covers nearly all nodes; avg deg ~12)
    int myc = (lane < deg) ? g_scol[start + lane] : 0;

    int m = deg < 32 ? deg : 32;
    for (int i = 0; i < m; i++) {
        int c = __shfl_sync(0xffffffffu, myc, i);
        float4 b = emb4[(size_t)c * 32 + lane];
        float p = a.x * b.x + a.y * b.y + a.z * b.z + a.w * b.w;
#pragma unroll
        for (int o = 16; o > 0; o >>= 1)
            p += __shfl_xor_sync(0xffffffffu, p, o);
        float w = expf(p);
        denom += w;
        acc.x = fmaf(w, b.x, acc.x);
        acc.y = fmaf(w, b.y, acc.y);
        acc.z = fmaf(w, b.z, acc.z);
        acc.w = fmaf(w, b.w, acc.w);
    }
    // rare tail for deg > 32
    for (int i = 32; i < deg; i++) {
        int c = g_scol[start + i];
        float4 b = emb4[(size_t)c * 32 + lane];
        float p = a.x * b.x + a.y * b.y + a.z * b.z + a.w * b.w;
#pragma unroll
        for (int o = 16; o > 0; o >>= 1)
            p += __shfl_xor_sync(0xffffffffu, p, o);
        float w = expf(p);
        denom += w;
        acc.x = fmaf(w, b.x, acc.x);
        acc.y = fmaf(w, b.y, acc.y);
        acc.z = fmaf(w, b.z, acc.z);
        acc.w = fmaf(w, b.w, acc.w);
    }

    reinterpret_cast<float4*>(agg)[(size_t)n * 32 + lane] = acc;
    if (lane == 0) g_denom[n] = denom;
}

// ---------------------------------------------------------------------------
// K5: per-row  x = [emb[i], agg[i]/denom[i]] @ W^T + b ; out = LayerNorm(x)
// (unchanged from R2: FFMA/LSU balanced, ~91us floor)
// ---------------------------------------------------------------------------
#define TILE_R 32
#define GEMM_SMEM_BYTES ((256 * 128 + TILE_R * 256) * 4)

__global__ void __launch_bounds__(256, 1)
gemm_ln_kernel(const float* __restrict__ emb,
               const float* __restrict__ W,
               const float* __restrict__ bias,
               const float* __restrict__ gamma,
               const float* __restrict__ beta,
               float* __restrict__ out /* in: agg, out: final */) {
    extern __shared__ float smem[];
    float* Ws = smem;              // [256][128]  Ws[k*128+j] = W[j*256+k]
    float* xs = smem + 256 * 128;  // [32][256] row-major x_cat tile

    const int tid = threadIdx.x;
    const int jq = tid & 31;
    const int rq = tid >> 5;

    for (int idx = tid; idx < 128 * 256; idx += 256) {
        int j = idx >> 8;
        int k = idx & 255;
        Ws[k * 128 + j] = W[idx];
    }
    __syncthreads();

    const int ntiles = (N_NODES + TILE_R - 1) / TILE_R;
    for (int tile = blockIdx.x; tile < ntiles; tile += gridDim.x) {
        const int row0 = tile * TILE_R;

#pragma unroll
        for (int i = 0; i < 4; i++) {
            int r = rq * 4 + i;
            int row = row0 + r;
            float4 e4, a4;
            if (row < N_NODES) {
                e4 = reinterpret_cast<const float4*>(emb)[(size_t)row * 32 + jq];
                float inv_d = 1.0f / (g_denom[row] + 1e-20f);
                a4 = reinterpret_cast<const float4*>(out)[(size_t)row * 32 + jq];
                a4.x *= inv_d; a4.y *= inv_d; a4.z *= inv_d; a4.w *= inv_d;
            } else {
                e4 = make_float4(0.f, 0.f, 0.f, 0.f);
                a4 = e4;
            }
            reinterpret_cast<float4*>(xs + r * 256)[jq] = e4;
            reinterpret_cast<float4*>(xs + r * 256 + 128)[jq] = a4;
        }
        __syncthreads();

        float acc[4][4];
#pragma unroll
        for (int i = 0; i < 4; i++)
#pragma unroll
            for (int jj = 0; jj < 4; jj++) acc[i][jj] = 0.f;

#pragma unroll 4
        for (int k = 0; k < 256; k++) {
            const float4 w4 =
                *reinterpret_cast<const float4*>(&Ws[(k << 7) + (jq << 2)]);
#pragma unroll
            for (int i = 0; i < 4; i++) {
                float xv = xs[((rq << 2) + i) * 256 + k];
                acc[i][0] = fmaf(xv, w4.x, acc[i][0]);
                acc[i][1] = fmaf(xv, w4.y, acc[i][1]);
                acc[i][2] = fmaf(xv, w4.z, acc[i][2]);
                acc[i][3] = fmaf(xv, w4.w, acc[i][3]);
            }
        }
        __syncthreads();

        const float4 b4 = reinterpret_cast<const float4*>(bias)[jq];
#pragma unroll
        for (int i = 0; i < 4; i++) {
            int r = rq * 4 + i;
            float4 v;
            v.x = acc[i][0] + b4.x;
            v.y = acc[i][1] + b4.y;
            v.z = acc[i][2] + b4.z;
            v.w = acc[i][3] + b4.w;
            reinterpret_cast<float4*>(xs + r * 128)[jq] = v;
        }
        __syncthreads();

        const float4 g4 = reinterpret_cast<const float4*>(gamma)[jq];
        const float4 be4 = reinterpret_cast<const float4*>(beta)[jq];
#pragma unroll
        for (int i = 0; i < 4; i++) {
            int r = rq * 4 + i;
            int row = row0 + r;
            float4 v = reinterpret_cast<float4*>(xs + r * 128)[jq];
            float s = v.x + v.y + v.z + v.w;
            float sq = v.x * v.x + v.y * v.y + v.z * v.z + v.w * v.w;
#pragma unroll
            for (int o = 16; o > 0; o >>= 1) {
                s += __shfl_xor_sync(0xffffffffu, s, o);
                sq += __shfl_xor_sync(0xffffffffu, sq, o);
            }
            float mu = s * (1.0f / 128.0f);
            float var = sq * (1.0f / 128.0f) - mu * mu;
            float rs = rsqrtf(var + 1e-5f);
            if (row < N_NODES) {
                float4 o4;
                o4.x = (v.x - mu) * rs * g4.x + be4.x;
                o4.y = (v.y - mu) * rs * g4.y + be4.y;
                o4.z = (v.z - mu) * rs * g4.z + be4.z;
                o4.w = (v.w - mu) * rs * g4.w + be4.w;
                reinterpret_cast<float4*>(out)[(size_t)row * 32 + jq] = o4;
            }
        }
        __syncthreads();
    }
}

// ---------------------------------------------------------------------------
extern "C" void kernel_launch(void* const* d_in, const int* in_sizes, int n_in,
                              void* d_out, int out_size) {
    const float* emb = (const float*)d_in[0];
    const int* edges = (const int*)d_in[1];  // int32 (JAX x64 disabled)
    const float* W = (const float*)d_in[2];
    const float* bias = (const float*)d_in[3];
    const float* gamma = (const float*)d_in[4];
    const float* beta = (const float*)d_in[5];
    float* out = (float*)d_out;

    (void)in_sizes; (void)n_in; (void)out_size;

    zero_cnt_kernel<<<98, 512>>>();
    hist_kernel<<<1172, 512>>>(edges);
    scan_kernel<<<1, 1024>>>();
    scatter_kernel<<<1172, 512>>>(edges);

    // one warp per node
    segment_kernel<<<(N_NODES * 32 + 255) / 256, 256>>>(
        reinterpret_cast<const float4*>(emb), out);

    cudaFuncSetAttribute(gemm_ln_kernel,
                         cudaFuncAttributeMaxDynamicSharedMemorySize,
                         GEMM_SMEM_BYTES);
    gemm_ln_kernel<<<148, 256, GEMM_SMEM_BYTES>>>(emb, W, bias, gamma, beta,
                                                  out);
}

// round 4
// speedup vs baseline: 1.3354x; 1.3354x over previous
#include <cuda_runtime.h>
#include <cstdint>

#define N_NODES 50000
#define N_EDGES 600000
#define DIM 128

typedef unsigned long long ull;

// Scratch: per-node attention denominator (sum of exp weights)
__device__ float g_denom[N_NODES];

// ---------------------------------------------------------------------------
// packed f32x2 helpers (SASS FFMA2 — only reachable via PTX fma.rn.f32x2)
// ---------------------------------------------------------------------------
__device__ __forceinline__ ull fma2(ull a, ull b, ull c) {
    ull d;
    asm("fma.rn.f32x2 %0, %1, %2, %3;" : "=l"(d) : "l"(a), "l"(b), "l"(c));
    return d;
}
__device__ __forceinline__ ull dup2(float x) {
    ull d;
    asm("mov.b64 %0, {%1, %1};" : "=l"(d) : "f"(x));
    return d;
}
__device__ __forceinline__ float2 unpack2(ull v) {
    float2 r;
    asm("mov.b64 {%0, %1}, %2;" : "=f"(r.x), "=f"(r.y) : "l"(v));
    return r;
}

// ---------------------------------------------------------------------------
// K0: zero the aggregation buffer (d_out doubles as agg scratch) and g_denom
// ---------------------------------------------------------------------------
__global__ void zero_kernel(float4* __restrict__ out4) {
    int idx = blockIdx.x * blockDim.x + threadIdx.x;
    int stride = gridDim.x * blockDim.x;
    const int n4 = N_NODES * DIM / 4;
    float4 z = make_float4(0.f, 0.f, 0.f, 0.f);
    for (int i = idx; i < n4; i += stride) out4[i] = z;
    for (int i = idx; i < N_NODES; i += stride) g_denom[i] = 0.f;
}

// ---------------------------------------------------------------------------
// K1: one warp per edge (R2 design — near L2 floor).
//   attn = exp(dot(emb[row], emb[col]))
//   denom[row] += attn            (scalar red)
//   agg[row]   += attn * emb[col] (vector red.v4)
// edges is int32 (JAX x64 disabled).
// ---------------------------------------------------------------------------
__global__ void edge_kernel(const float4* __restrict__ emb4,
                            const int* __restrict__ edges,
                            float* __restrict__ agg) {
    int gwarp = (blockIdx.x * blockDim.x + threadIdx.x) >> 5;
    int lane = threadIdx.x & 31;
    if (gwarp >= N_EDGES) return;

    int r = edges[gwarp];            // destination (segment) node
    int c = edges[N_EDGES + gwarp];  // source node
    if ((unsigned)r >= N_NODES || (unsigned)c >= N_NODES) return;

    float4 a = emb4[(size_t)r * 32 + lane];
    float4 b = emb4[(size_t)c * 32 + lane];

    float p = a.x * b.x + a.y * b.y + a.z * b.z + a.w * b.w;
#pragma unroll
    for (int o = 16; o > 0; o >>= 1)
        p += __shfl_xor_sync(0xffffffffu, p, o);

    float w = expf(p);

    if (lane == 0) atomicAdd(&g_denom[r], w);

    float vx = w * b.x, vy = w * b.y, vz = w * b.z, vw = w * b.w;
    float* dst = agg + (size_t)r * DIM + lane * 4;
    asm volatile("red.global.add.v4.f32 [%0], {%1, %2, %3, %4};"
                 :: "l"(dst), "f"(vx), "f"(vy), "f"(vz), "f"(vw)
                 : "memory");
}

// ---------------------------------------------------------------------------
// K2: per-row  x = [emb[i], agg[i]/denom[i]] @ W^T + b ; out = LayerNorm(x)
// Persistent blocks, W transposed in smem, 32-row tiles, 4x4 blocking,
// inner product via packed f32x2 FMA (2 cols per instruction).
// ---------------------------------------------------------------------------
#define TILE_R 32
#define GEMM_SMEM_BYTES ((256 * 128 + TILE_R * 256) * 4)

__global__ void __launch_bounds__(256, 1)
gemm_ln_kernel(const float* __restrict__ emb,
               const float* __restrict__ W,
               const float* __restrict__ bias,
               const float* __restrict__ gamma,
               const float* __restrict__ beta,
               float* __restrict__ out /* in: agg, out: final */) {
    extern __shared__ float smem[];
    float* Ws = smem;              // [256][128]  Ws[k*128+j] = W[j*256+k]
    float* xs = smem + 256 * 128;  // [32][256] row-major x_cat tile

    const int tid = threadIdx.x;
    const int jq = tid & 31;   // output-column group: cols [jq*4, jq*4+4)
    const int rq = tid >> 5;   // row group (warp id): rows [rq*4, rq*4+4)

    for (int idx = tid; idx < 128 * 256; idx += 256) {
        int j = idx >> 8;
        int k = idx & 255;
        Ws[k * 128 + j] = W[idx];
    }
    __syncthreads();

    const int ntiles = (N_NODES + TILE_R - 1) / TILE_R;
    for (int tile = blockIdx.x; tile < ntiles; tile += gridDim.x) {
        const int row0 = tile * TILE_R;

        // --- load x tile: warp rq loads rows rq*4 .. rq*4+3 ---
#pragma unroll
        for (int i = 0; i < 4; i++) {
            int r = rq * 4 + i;
            int row = row0 + r;
            float4 e4, a4;
            if (row < N_NODES) {
                e4 = reinterpret_cast<const float4*>(emb)[(size_t)row * 32 + jq];
                float inv_d = 1.0f / (g_denom[row] + 1e-20f);
                a4 = reinterpret_cast<const float4*>(out)[(size_t)row * 32 + jq];
                a4.x *= inv_d; a4.y *= inv_d; a4.z *= inv_d; a4.w *= inv_d;
            } else {
                e4 = make_float4(0.f, 0.f, 0.f, 0.f);
                a4 = e4;
            }
            reinterpret_cast<float4*>(xs + r * 256)[jq] = e4;
            reinterpret_cast<float4*>(xs + r * 256 + 128)[jq] = a4;
        }
        __syncthreads();

        // --- GEMM via f32x2: acc01/acc23 hold col pairs per row ---
        ull acc01[4], acc23[4];
#pragma unroll
        for (int i = 0; i < 4; i++) { acc01[i] = 0ull; acc23[i] = 0ull; }

#pragma unroll 2
        for (int k = 0; k < 256; k += 2) {
            const ull* w0 =
                reinterpret_cast<const ull*>(&Ws[(k << 7) + (jq << 2)]);
            const ull* w1 =
                reinterpret_cast<const ull*>(&Ws[((k + 1) << 7) + (jq << 2)]);
            ull w01_0 = w0[0], w23_0 = w0[1];
            ull w01_1 = w1[0], w23_1 = w1[1];
#pragma unroll
            for (int i = 0; i < 4; i++) {
                float2 xv = *reinterpret_cast<const float2*>(
                    &xs[((rq << 2) + i) * 256 + k]);
                ull x0 = dup2(xv.x);
                ull x1 = dup2(xv.y);
                acc01[i] = fma2(x0, w01_0, acc01[i]);
                acc23[i] = fma2(x0, w23_0, acc23[i]);
                acc01[i] = fma2(x1, w01_1, acc01[i]);
                acc23[i] = fma2(x1, w23_1, acc23[i]);
            }
        }
        __syncthreads();  // done reading xs; reuse as x-output buffer

        // --- add bias, stash x tile [32][128] into smem for LN ---
        const float4 b4 = reinterpret_cast<const float4*>(bias)[jq];
#pragma unroll
        for (int i = 0; i < 4; i++) {
            int r = rq * 4 + i;
            float2 v01 = unpack2(acc01[i]);
            float2 v23 = unpack2(acc23[i]);
            float4 v;
            v.x = v01.x + b4.x;
            v.y = v01.y + b4.y;
            v.z = v23.x + b4.z;
            v.w = v23.y + b4.w;
            reinterpret_cast<float4*>(xs + r * 128)[jq] = v;
        }
        __syncthreads();

        // --- LayerNorm: warp rq normalizes rows rq*4 .. rq*4+3 ---
        const float4 g4 = reinterpret_cast<const float4*>(gamma)[jq];
        const float4 be4 = reinterpret_cast<const float4*>(beta)[jq];
#pragma unroll
        for (int i = 0; i < 4; i++) {
            int r = rq * 4 + i;
            int row = row0 + r;
            float4 v = reinterpret_cast<float4*>(xs + r * 128)[jq];
            float s = v.x + v.y + v.z + v.w;
            float sq = v.x * v.x + v.y * v.y + v.z * v.z + v.w * v.w;
#pragma unroll
            for (int o = 16; o > 0; o >>= 1) {
                s += __shfl_xor_sync(0xffffffffu, s, o);
                sq += __shfl_xor_sync(0xffffffffu, sq, o);
            }
            float mu = s * (1.0f / 128.0f);
            float var = sq * (1.0f / 128.0f) - mu * mu;
            float rs = rsqrtf(var + 1e-5f);
            if (row < N_NODES) {
                float4 o4;
                o4.x = (v.x - mu) * rs * g4.x + be4.x;
                o4.y = (v.y - mu) * rs * g4.y + be4.y;
                o4.z = (v.z - mu) * rs * g4.z + be4.z;
                o4.w = (v.w - mu) * rs * g4.w + be4.w;
                reinterpret_cast<float4*>(out)[(size_t)row * 32 + jq] = o4;
            }
        }
        __syncthreads();  // before next tile overwrites xs
    }
}

// ---------------------------------------------------------------------------
extern "C" void kernel_launch(void* const* d_in, const int* in_sizes, int n_in,
                              void* d_out, int out_size) {
    const float* emb = (const float*)d_in[0];
    const int* edges = (const int*)d_in[1];  // int32 (JAX x64 disabled)
    const float* W = (const float*)d_in[2];
    const float* bias = (const float*)d_in[3];
    const float* gamma = (const float*)d_in[4];
    const float* beta = (const float*)d_in[5];
    float* out = (float*)d_out;

    (void)in_sizes; (void)n_in; (void)out_size;

    // K0: zero agg (in d_out) + denom
    zero_kernel<<<4096, 256>>>(reinterpret_cast<float4*>(out));

    // K1: edge attention + scatter-add (1 warp / edge)
    {
        int total_threads = N_EDGES * 32;
        int threads = 256;
        int blocks = (total_threads + threads - 1) / threads;
        edge_kernel<<<blocks, threads>>>(reinterpret_cast<const float4*>(emb),
                                         edges, out);
    }

    // K2: fused normalize + concat-GEMM + LayerNorm (persistent grid)
    cudaFuncSetAttribute(gemm_ln_kernel,
                         cudaFuncAttributeMaxDynamicSharedMemorySize,
                         GEMM_SMEM_BYTES);
    gemm_ln_kernel<<<148, 256, GEMM_SMEM_BYTES>>>(emb, W, bias, gamma, beta,
                                                  out);
}

// round 5
// speedup vs baseline: 1.9107x; 1.4308x over previous
#include <cuda_runtime.h>
#include <cstdint>

#define N_NODES 50000
#define N_EDGES 600000
#define DIM 128

// Scratch: per-node attention denominator (sum of exp weights)
__device__ float g_denom[N_NODES];

// ---------------------------------------------------------------------------
// helpers
// ---------------------------------------------------------------------------
// pack two f32 into bf16x2: x0 -> low 16 bits, x1 -> high 16 bits
__device__ __forceinline__ uint32_t pack2bf(float x0, float x1) {
    uint32_t d;
    asm("cvt.rn.bf16x2.f32 %0, %1, %2;" : "=r"(d) : "f"(x1), "f"(x0));
    return d;
}
// reconstruct the f32 values represented by a bf16x2
__device__ __forceinline__ float bflo_f32(uint32_t p) {
    return __uint_as_float(p << 16);
}
__device__ __forceinline__ float bfhi_f32(uint32_t p) {
    return __uint_as_float(p & 0xFFFF0000u);
}

__device__ __forceinline__ void mma_bf16(float* c, uint32_t a0, uint32_t a1,
                                         uint32_t a2, uint32_t a3,
                                         uint32_t b0, uint32_t b1) {
    asm volatile(
        "mma.sync.aligned.m16n8k16.row.col.f32.bf16.bf16.f32 "
        "{%0,%1,%2,%3}, {%4,%5,%6,%7}, {%8,%9}, {%0,%1,%2,%3};"
        : "+f"(c[0]), "+f"(c[1]), "+f"(c[2]), "+f"(c[3])
        : "r"(a0), "r"(a1), "r"(a2), "r"(a3), "r"(b0), "r"(b1));
}

// ---------------------------------------------------------------------------
// K0: zero the aggregation buffer (d_out doubles as agg scratch) and g_denom
// ---------------------------------------------------------------------------
__global__ void zero_kernel(float4* __restrict__ out4) {
    int idx = blockIdx.x * blockDim.x + threadIdx.x;
    int stride = gridDim.x * blockDim.x;
    const int n4 = N_NODES * DIM / 4;
    float4 z = make_float4(0.f, 0.f, 0.f, 0.f);
    for (int i = idx; i < n4; i += stride) out4[i] = z;
    for (int i = idx; i < N_NODES; i += stride) g_denom[i] = 0.f;
}

// ---------------------------------------------------------------------------
// K1: one warp per edge (near L2 floor).
// ---------------------------------------------------------------------------
__global__ void edge_kernel(const float4* __restrict__ emb4,
                            const int* __restrict__ edges,
                            float* __restrict__ agg) {
    int gwarp = (blockIdx.x * blockDim.x + threadIdx.x) >> 5;
    int lane = threadIdx.x & 31;
    if (gwarp >= N_EDGES) return;

    int r = edges[gwarp];            // destination (segment) node
    int c = edges[N_EDGES + gwarp];  // source node
    if ((unsigned)r >= N_NODES || (unsigned)c >= N_NODES) return;

    float4 a = emb4[(size_t)r * 32 + lane];
    float4 b = emb4[(size_t)c * 32 + lane];

    float p = a.x * b.x + a.y * b.y + a.z * b.z + a.w * b.w;
#pragma unroll
    for (int o = 16; o > 0; o >>= 1)
        p += __shfl_xor_sync(0xffffffffu, p, o);

    float w = expf(p);

    if (lane == 0) atomicAdd(&g_denom[r], w);

    float vx = w * b.x, vy = w * b.y, vz = w * b.z, vw = w * b.w;
    float* dst = agg + (size_t)r * DIM + lane * 4;
    asm volatile("red.global.add.v4.f32 [%0], {%1, %2, %3, %4};"
                 :: "l"(dst), "f"(vx), "f"(vy), "f"(vz), "f"(vw)
                 : "memory");
}

// ---------------------------------------------------------------------------
// K2: tensor-core GEMM + LayerNorm.
//   x[row] = [emb[row], agg[row]/denom[row]]  (256 wide)
//   out[row] = LN(x @ W^T + b)
// bf16 2-term split: D = xh*Wh + xh*Wl + xl*Wh  (~1e-6 rel err)
// Block tile: 64 rows x 128 cols, K=256. 8 warps: warp w -> rows 16*(w%4),
// cols 64*(w/4). mma m16n8k16. Packed k-pair smem with stride 132 words
// (bank = 4*row + k2 per quad -> conflict free).
// ---------------------------------------------------------------------------
#define TILE_R 64
#define WSTRIDE 132
#define SM_WPH 0                       // [128][132] u32
#define SM_WPL (128 * WSTRIDE)         // [128][132] u32
#define SM_XPH (2 * 128 * WSTRIDE)     // [64][132] u32
#define SM_XPL (2 * 128 * WSTRIDE + 64 * WSTRIDE)
#define SMEM_WORDS (2 * 128 * WSTRIDE + 2 * 64 * WSTRIDE)
#define GEMM_SMEM_BYTES (SMEM_WORDS * 4)

__global__ void __launch_bounds__(256, 1)
gemm_ln_kernel(const float* __restrict__ emb,
               const float* __restrict__ W,
               const float* __restrict__ bias,
               const float* __restrict__ gamma,
               const float* __restrict__ beta,
               float* __restrict__ out /* in: agg, out: final */) {
    extern __shared__ uint32_t smem[];
    uint32_t* Wph = smem + SM_WPH;
    uint32_t* Wpl = smem + SM_WPL;
    uint32_t* xph = smem + SM_XPH;
    uint32_t* xpl = smem + SM_XPL;
    float* os = reinterpret_cast<float*>(smem + SM_XPH);  // [64][128] reuse

    const int tid = threadIdx.x;
    const int lane = tid & 31;
    const int wid = tid >> 5;
    const int g = lane >> 2;    // group id (0..7)
    const int tig = lane & 3;   // thread in group

    // ---- stage W split into smem (once per block) ----
    // (n, k2) pairs: n=0..127 (output col), k2=0..127 (k pair index)
    for (int idx = tid; idx < 128 * 128; idx += 256) {
        int n = idx >> 7;
        int k2 = idx & 127;
        float2 w2 = *reinterpret_cast<const float2*>(&W[n * 256 + 2 * k2]);
        uint32_t ph = pack2bf(w2.x, w2.y);
        float l0 = w2.x - bflo_f32(ph);
        float l1 = w2.y - bfhi_f32(ph);
        uint32_t pl = pack2bf(l0, l1);
        Wph[n * WSTRIDE + k2] = ph;
        Wpl[n * WSTRIDE + k2] = pl;
    }
    __syncthreads();

    const int mwarp = wid & 3;  // row group (0..3) -> rows 16*mwarp
    const int nwarp = wid >> 2; // col group (0..1) -> cols 64*nwarp
    const int n0 = nwarp * 64;
    const int arow = mwarp * 16 + g;

    const int ntiles = (N_NODES + TILE_R - 1) / TILE_R;
    for (int tile = blockIdx.x; tile < ntiles; tile += gridDim.x) {
        const int row0 = tile * TILE_R;

        // ---- stage x tile: warp wid handles rows wid*8 .. wid*8+7 ----
#pragma unroll
        for (int i = 0; i < 8; i++) {
            int r = wid * 8 + i;
            int row = row0 + r;
            float4 e4, a4;
            if (row < N_NODES) {
                e4 = reinterpret_cast<const float4*>(emb)[(size_t)row * 32 + lane];
                float inv_d = 1.0f / (g_denom[row] + 1e-20f);
                a4 = reinterpret_cast<const float4*>(out)[(size_t)row * 32 + lane];
                a4.x *= inv_d; a4.y *= inv_d; a4.z *= inv_d; a4.w *= inv_d;
            } else {
                e4 = make_float4(0.f, 0.f, 0.f, 0.f);
                a4 = e4;
            }
            // emb -> k2 = 2*lane, 2*lane+1 ; agg -> k2 = 64+2*lane, +1
            uint32_t ph0 = pack2bf(e4.x, e4.y);
            uint32_t ph1 = pack2bf(e4.z, e4.w);
            uint32_t pl0 = pack2bf(e4.x - bflo_f32(ph0), e4.y - bfhi_f32(ph0));
            uint32_t pl1 = pack2bf(e4.z - bflo_f32(ph1), e4.w - bfhi_f32(ph1));
            xph[r * WSTRIDE + 2 * lane] = ph0;
            xph[r * WSTRIDE + 2 * lane + 1] = ph1;
            xpl[r * WSTRIDE + 2 * lane] = pl0;
            xpl[r * WSTRIDE + 2 * lane + 1] = pl1;

            uint32_t qh0 = pack2bf(a4.x, a4.y);
            uint32_t qh1 = pack2bf(a4.z, a4.w);
            uint32_t ql0 = pack2bf(a4.x - bflo_f32(qh0), a4.y - bfhi_f32(qh0));
            uint32_t ql1 = pack2bf(a4.z - bflo_f32(qh1), a4.w - bfhi_f32(qh1));
            xph[r * WSTRIDE + 64 + 2 * lane] = qh0;
            xph[r * WSTRIDE + 64 + 2 * lane + 1] = qh1;
            xpl[r * WSTRIDE + 64 + 2 * lane] = ql0;
            xpl[r * WSTRIDE + 64 + 2 * lane + 1] = ql1;
        }
        __syncthreads();

        // ---- mma mainloop ----
        float acc[8][4];
#pragma unroll
        for (int nt = 0; nt < 8; nt++)
#pragma unroll
            for (int q = 0; q < 4; q++) acc[nt][q] = 0.f;

#pragma unroll
        for (int ks = 0; ks < 16; ks++) {
            const int kb = ks * 8;
            uint32_t ah0 = xph[arow * WSTRIDE + kb + tig];
            uint32_t ah1 = xph[(arow + 8) * WSTRIDE + kb + tig];
            uint32_t ah2 = xph[arow * WSTRIDE + kb + tig + 4];
            uint32_t ah3 = xph[(arow + 8) * WSTRIDE + kb + tig + 4];
            uint32_t al0 = xpl[arow * WSTRIDE + kb + tig];
            uint32_t al1 = xpl[(arow + 8) * WSTRIDE + kb + tig];
            uint32_t al2 = xpl[arow * WSTRIDE + kb + tig + 4];
            uint32_t al3 = xpl[(arow + 8) * WSTRIDE + kb + tig + 4];
#pragma unroll
            for (int nt = 0; nt < 8; nt++) {
                int brow = n0 + nt * 8 + g;
                uint32_t bh0 = Wph[brow * WSTRIDE + kb + tig];
                uint32_t bh1 = Wph[brow * WSTRIDE + kb + tig + 4];
                uint32_t bl0 = Wpl[brow * WSTRIDE + kb + tig];
                uint32_t bl1 = Wpl[brow * WSTRIDE + kb + tig + 4];
                mma_bf16(acc[nt], ah0, ah1, ah2, ah3, bh0, bh1);
                mma_bf16(acc[nt], ah0, ah1, ah2, ah3, bl0, bl1);
                mma_bf16(acc[nt], al0, al1, al2, al3, bh0, bh1);
            }
        }
        __syncthreads();  // all warps done reading xph/xpl before os reuse

        // ---- write accums to smem [64][128] ----
#pragma unroll
        for (int nt = 0; nt < 8; nt++) {
            int ccol = n0 + nt * 8 + 2 * tig;
            int crow = mwarp * 16 + g;
            *reinterpret_cast<float2*>(&os[crow * 128 + ccol]) =
                make_float2(acc[nt][0], acc[nt][1]);
            *reinterpret_cast<float2*>(&os[(crow + 8) * 128 + ccol]) =
                make_float2(acc[nt][2], acc[nt][3]);
        }
        __syncthreads();

        // ---- LayerNorm: warp wid handles rows wid*8 .. wid*8+7 ----
        const float4 b4 = reinterpret_cast<const float4*>(bias)[lane];
        const float4 g4 = reinterpret_cast<const float4*>(gamma)[lane];
        const float4 be4 = reinterpret_cast<const float4*>(beta)[lane];
#pragma unroll
        for (int i = 0; i < 8; i++) {
            int r = wid * 8 + i;
            int row = row0 + r;
            float4 v = reinterpret_cast<float4*>(os)[r * 32 + lane];
            v.x += b4.x; v.y += b4.y; v.z += b4.z; v.w += b4.w;
            float s = v.x + v.y + v.z + v.w;
            float sq = v.x * v.x + v.y * v.y + v.z * v.z + v.w * v.w;
#pragma unroll
            for (int o = 16; o > 0; o >>= 1) {
                s += __shfl_xor_sync(0xffffffffu, s, o);
                sq += __shfl_xor_sync(0xffffffffu, sq, o);
            }
            float mu = s * (1.0f / 128.0f);
            float var = sq * (1.0f / 128.0f) - mu * mu;
            float rs = rsqrtf(var + 1e-5f);
            if (row < N_NODES) {
                float4 o4;
                o4.x = (v.x - mu) * rs * g4.x + be4.x;
                o4.y = (v.y - mu) * rs * g4.y + be4.y;
                o4.z = (v.z - mu) * rs * g4.z + be4.z;
                o4.w = (v.w - mu) * rs * g4.w + be4.w;
                reinterpret_cast<float4*>(out)[(size_t)row * 32 + lane] = o4;
            }
        }
        __syncthreads();  // before next tile overwrites xph/os
    }
}

// ---------------------------------------------------------------------------
extern "C" void kernel_launch(void* const* d_in, const int* in_sizes, int n_in,
                              void* d_out, int out_size) {
    const float* emb = (const float*)d_in[0];
    const int* edges = (const int*)d_in[1];  // int32 (JAX x64 disabled)
    const float* W = (const float*)d_in[2];
    const float* bias = (const float*)d_in[3];
    const float* gamma = (const float*)d_in[4];
    const float* beta = (const float*)d_in[5];
    float* out = (float*)d_out;

    (void)in_sizes; (void)n_in; (void)out_size;

    zero_kernel<<<4096, 256>>>(reinterpret_cast<float4*>(out));

    {
        int total_threads = N_EDGES * 32;
        int threads = 256;
        int blocks = (total_threads + threads - 1) / threads;
        edge_kernel<<<blocks, threads>>>(reinterpret_cast<const float4*>(emb),
                                         edges, out);
    }

    cudaFuncSetAttribute(gemm_ln_kernel,
                         cudaFuncAttributeMaxDynamicSharedMemorySize,
                         GEMM_SMEM_BYTES);
    gemm_ln_kernel<<<148, 256, GEMM_SMEM_BYTES>>>(emb, W, bias, gamma, beta,
                                                  out);
}